// round 15
// baseline (speedup 1.0000x reference)
#include <cuda_runtime.h>
#include <cstdint>

#define B_ 32
#define P_ 24
#define S_ 48
#define H_ 512
#define F_ 64
#define D_ 576    // H + F
#define G4_ 2048  // 4*H
#define O_ 16
#define EPS_ 1e-5f
#define NCTA_ 64        // lstm CTAs
#define GXCTA_ 128      // gx CTAs

// ---------------- scratch (device globals, no allocation) ----------------
__device__ float g_seq[P_ * B_ * D_];     // rep, layout [t][b][d]
__device__ float g_Gx[P_ * B_ * G4_];     // input projection + bias, [t][b][n]
__device__ float g_h[2][B_ * H_];         // ping-pong hidden
__device__ float g_hb[B_ * H_];           // backward first-step hidden
__device__ int   g_bar;                   // grid barrier counter (reset in gxbwd)

__device__ __forceinline__ float sigf(float x) { return 1.f / (1.f + expf(-x)); }
__device__ __forceinline__ float wred(float v) {
    #pragma unroll
    for (int o = 16; o; o >>= 1) v += __shfl_xor_sync(0xffffffffu, v, o);
    return v;
}
__device__ __forceinline__ void wred4(float& a, float& b, float& c, float& d) {
    #pragma unroll
    for (int o = 16; o; o >>= 1) {
        a += __shfl_xor_sync(0xffffffffu, a, o);
        b += __shfl_xor_sync(0xffffffffu, b, o);
        c += __shfl_xor_sync(0xffffffffu, c, o);
        d += __shfl_xor_sync(0xffffffffu, d, o);
    }
}
__device__ __forceinline__ int num_valid(const int* lens) {
    int nv = 0;
    while (nv < B_ && lens[nv] == P_) nv++;
    return nv;
}

// ---------------- K1: attention; grid (P, 4); pipelined cp.async -------------
// (measured 9.0us, unchanged)
__global__ __launch_bounds__(512) void attn_rep_kernel(
    const int* __restrict__ x, const int* __restrict__ xmask,
    const float* __restrict__ xfeat, const int* __restrict__ lens,
    const float* __restrict__ emb, const float* __restrict__ wattn,
    const float* __restrict__ battn)
{
    int p = blockIdx.x;          // 0..23
    int b = blockIdx.y;          // 0..3  (valid batches are a prefix)
    int nv = num_valid(lens);
    if (b >= nv) return;
    int bmax = (b == 3) ? nv : (b + 1);

    extern __shared__ float sm1[];
    float* E     = sm1;               // S*H = 24576
    float* xfs   = E + S_ * H_;       // S*F = 3072
    float* wv    = xfs + S_ * F_;     // 512
    float* sc    = wv + H_;           // 48
    float* alpha = sc + S_;           // 48
    int*   msk   = (int*)(alpha + S_);// 48

    int tid = threadIdx.x;
    int warp = tid >> 5, lane = tid & 31;
    for (int i = tid; i < H_; i += 512) wv[i] = wattn[i];

    for (; b < bmax; b++) {
        int bp = b * P_ + p;
        if (tid < S_) msk[tid] = (xmask[bp * S_ + tid] != 0);  // int32 or f32 bool

        #pragma unroll
        for (int it = 0; it < 6; it++) {
            int idx = tid + it * 512;
            int row = idx >> 7;
            int c4  = idx & 127;
            int tok = __ldg(&x[bp * S_ + row]);
            const float4* src = (const float4*)emb + (size_t)tok * 128 + c4;
            unsigned daddr = (unsigned)__cvta_generic_to_shared(E + idx * 4);
            asm volatile("cp.async.cg.shared.global [%0], [%1], 16;"
                         :: "r"(daddr), "l"(src));
        }
        asm volatile("cp.async.commit_group;");
        #pragma unroll
        for (int it = 6; it < 12; it++) {
            int idx = tid + it * 512;
            int row = idx >> 7;
            int c4  = idx & 127;
            int tok = __ldg(&x[bp * S_ + row]);
            const float4* src = (const float4*)emb + (size_t)tok * 128 + c4;
            unsigned daddr = (unsigned)__cvta_generic_to_shared(E + idx * 4);
            asm volatile("cp.async.cg.shared.global [%0], [%1], 16;"
                         :: "r"(daddr), "l"(src));
        }
        asm volatile("cp.async.commit_group;");
        {
            const float4* xsrc = (const float4*)(xfeat + (size_t)bp * S_ * F_);
            #pragma unroll
            for (int it = 0; it < 2; it++) {
                int idx = tid + it * 512;
                if (idx < 768) {
                    unsigned daddr = (unsigned)__cvta_generic_to_shared(xfs + idx * 4);
                    asm volatile("cp.async.cg.shared.global [%0], [%1], 16;"
                                 :: "r"(daddr), "l"(xsrc + idx));
                }
            }
        }
        asm volatile("cp.async.commit_group;");

        asm volatile("cp.async.wait_group 2;" ::: "memory");
        __syncthreads();
        for (int s = warp; s < 24; s += 16) {
            float acc = 0.f;
            for (int k = lane; k < H_; k += 32) acc += E[s * H_ + k] * wv[k];
            acc = wred(acc);
            if (lane == 0) sc[s] = msk[s] ? -1e30f : (acc + battn[0]);
        }
        asm volatile("cp.async.wait_group 1;" ::: "memory");
        __syncthreads();
        for (int s = 24 + warp; s < S_; s += 16) {
            float acc = 0.f;
            for (int k = lane; k < H_; k += 32) acc += E[s * H_ + k] * wv[k];
            acc = wred(acc);
            if (lane == 0) sc[s] = msk[s] ? -1e30f : (acc + battn[0]);
        }
        __syncthreads();

        if (warp == 0) {
            float v0 = sc[lane];
            float v1 = (lane < 16) ? sc[32 + lane] : -3e38f;
            float m = fmaxf(v0, v1);
            #pragma unroll
            for (int o = 16; o; o >>= 1)
                m = fmaxf(m, __shfl_xor_sync(0xffffffffu, m, o));
            float e0 = expf(v0 - m);
            float e1 = (lane < 16) ? expf(v1 - m) : 0.f;
            float ssum = wred(e0 + e1);
            float inv = 1.f / ssum;
            alpha[lane] = msk[lane] ? 0.f : e0 * inv;
            if (lane < 16) alpha[32 + lane] = msk[32 + lane] ? 0.f : e1 * inv;
        }
        __syncthreads();

        float* outrow = &g_seq[(p * B_ + b) * D_];
        {
            int h = tid;   // 512 threads == H
            float acc = 0.f;
            #pragma unroll 8
            for (int s = 0; s < S_; s++) acc += alpha[s] * E[s * H_ + h];
            outrow[h] = acc;
        }
        if (tid < F_) {
            asm volatile("cp.async.wait_group 0;" ::: "memory");
            float acc = 0.f;
            #pragma unroll 8
            for (int s = 0; s < S_; s++)
                if (!msk[s]) acc += xfs[s * F_ + tid];
            outrow[H_ + tid] = acc;
        }
        asm volatile("cp.async.wait_group 0;" ::: "memory");
        __syncthreads();
    }
}

// ---------------- K2: Gx projection (CTAs 0..127) + backward step (128..191) --
// (R14 version — measured good)
__global__ __launch_bounds__(256) void gxbwd_kernel(
    const int* __restrict__ lens,
    const float* __restrict__ Wih_f, const float* __restrict__ bih_f,
    const float* __restrict__ bhh_f,
    const float* __restrict__ Wih_b, const float* __restrict__ bih_b,
    const float* __restrict__ bhh_b)
{
    int tid = threadIdx.x, warp = tid >> 5, lane = tid & 31;
    int nv = num_valid(lens);
    if (tid == 0 && blockIdx.x == 0) g_bar = 0;   // reset grid barrier for lstm

    if (blockIdx.x < GXCTA_) {
        extern __shared__ float sseq[];   // [24][2][576]
        for (int b0 = 0; b0 < nv; b0 += 2) {
            int bc = (nv - b0) < 2 ? (nv - b0) : 2;
            for (int q = tid; q < P_ * bc * 144; q += 256) {
                int t  = q / (bc * 144);
                int r  = q - t * (bc * 144);
                int bb = r / 144;
                int c4 = r - bb * 144;
                ((float4*)sseq)[(t * 2 + bb) * 144 + c4] =
                    ((const float4*)g_seq)[((size_t)(t * B_ + b0 + bb)) * 144 + c4];
            }
            __syncthreads();

            #pragma unroll
            for (int nn = 0; nn < 2; nn++) {
                int n = blockIdx.x * 16 + warp * 2 + nn;
                float wreg[18];
                #pragma unroll
                for (int i = 0; i < 18; i++)
                    wreg[i] = Wih_f[(size_t)n * D_ + lane + 32 * i];
                float bias = bih_f[n] + bhh_f[n];
                for (int t0 = 0; t0 < P_; t0 += 4) {
                    for (int bb = 0; bb < bc; bb++) {
                        const float* s0 = &sseq[((t0 + 0) * 2 + bb) * D_];
                        const float* s1 = &sseq[((t0 + 1) * 2 + bb) * D_];
                        const float* s2 = &sseq[((t0 + 2) * 2 + bb) * D_];
                        const float* s3 = &sseq[((t0 + 3) * 2 + bb) * D_];
                        float a0 = 0, a1 = 0, a2 = 0, a3 = 0;
                        #pragma unroll
                        for (int i = 0; i < 18; i++) {
                            float w = wreg[i];
                            int kk = lane + 32 * i;
                            a0 += w * s0[kk];
                            a1 += w * s1[kk];
                            a2 += w * s2[kk];
                            a3 += w * s3[kk];
                        }
                        wred4(a0, a1, a2, a3);
                        if (lane == 0) {
                            int b = b0 + bb;
                            g_Gx[((size_t)(t0 + 0) * B_ + b) * G4_ + n] = a0 + bias;
                            g_Gx[((size_t)(t0 + 1) * B_ + b) * G4_ + n] = a1 + bias;
                            g_Gx[((size_t)(t0 + 2) * B_ + b) * G4_ + n] = a2 + bias;
                            g_Gx[((size_t)(t0 + 3) * B_ + b) * G4_ + n] = a3 + bias;
                        }
                    }
                }
            }
            __syncthreads();
        }
    } else {
        // ---- backward single-step path (h0=c0=0): 64 CTAs x 8 warps ----
        int j = (blockIdx.x - GXCTA_) * 8 + warp;
        const float4* wi4 = (const float4*)(Wih_b + (size_t)j * D_);
        const float4* wg4 = (const float4*)(Wih_b + (size_t)(2 * H_ + j) * D_);
        const float4* wo4 = (const float4*)(Wih_b + (size_t)(3 * H_ + j) * D_);

        for (int b = 0; b < nv; b++) {
            const float4* xr4 = (const float4*)&g_seq[((P_ - 1) * B_ + b) * D_];
            float ai = 0, ag = 0, ao = 0;
            #pragma unroll
            for (int u = 0; u < 5; u++) {
                int i = lane + 32 * u;
                if (i < 144) {
                    float4 xv = xr4[i];
                    float4 a = wi4[i]; ai += a.x*xv.x + a.y*xv.y + a.z*xv.z + a.w*xv.w;
                    float4 c = wg4[i]; ag += c.x*xv.x + c.y*xv.y + c.z*xv.z + c.w*xv.w;
                    float4 d = wo4[i]; ao += d.x*xv.x + d.y*xv.y + d.z*xv.z + d.w*xv.w;
                }
            }
            float dummy = 0.f;
            wred4(ai, ag, ao, dummy);
            if (lane == 0) {
                float bi = bih_b[j] + bhh_b[j];
                float bg = bih_b[2 * H_ + j] + bhh_b[2 * H_ + j];
                float bo = bih_b[3 * H_ + j] + bhh_b[3 * H_ + j];
                float cnew = sigf(ai + bi) * tanhf(ag + bg);   // c_prev = 0
                g_hb[b * H_ + j] = sigf(ao + bo) * tanhf(cnew);
            }
        }
    }
}

// ---------------- K3: fused 24-step LSTM + final head (persistent) -----------
// Merged-batch inner loop: 16 accumulators, one sweep; lane bb finishes batch bb.
__global__ __launch_bounds__(256) void lstm_fused_kernel(
    const int* __restrict__ lens, const float* __restrict__ Whh,
    const float* __restrict__ Wfc, const float* __restrict__ bfc,
    const float* __restrict__ gamma, const float* __restrict__ beta,
    float* __restrict__ out)
{
    extern __shared__ float sm[];
    float* hbuf = sm;                 // [4][512] = 2048 floats
    float* scll = sm + 4 * H_;        // c state [8 warps][32 b]
    int k = blockIdx.x, tid = threadIdx.x, warp = tid >> 5, lane = tid & 31;

    int nv = num_valid(lens);
    int j = k * 8 + warp;

    float wr[64];
    #pragma unroll
    for (int g = 0; g < 4; g++) {
        const float* row = Whh + (size_t)(g * H_ + j) * H_;
        #pragma unroll
        for (int i = 0; i < 16; i++)
            wr[g * 16 + i] = __ldg(&row[lane + 32 * i]);
    }
    // zero hbuf so bb >= bc garbage reads are finite (avoid NaN FMA slowdowns)
    for (int q = tid; q < 4 * H_; q += 256) hbuf[q] = 0.f;

    for (int t = 0; t < P_; t++) {
        const float* hsrc = g_h[t & 1];
        float* hdst = g_h[(t + 1) & 1];

        for (int b0 = 0; b0 < nv; b0 += 4) {
            int bc = (nv - b0) < 4 ? (nv - b0) : 4;

            // Gx prefetch: lane bb (bb<bc) loads its own 4 gate values
            float pgi = 0, pgf = 0, pgg = 0, pgo = 0;
            if (lane < bc) {
                const float* gx = &g_Gx[((size_t)t * B_ + b0 + lane) * G4_];
                pgi = __ldcg(&gx[j]);
                pgf = __ldcg(&gx[H_ + j]);
                pgg = __ldcg(&gx[2 * H_ + j]);
                pgo = __ldcg(&gx[3 * H_ + j]);
            }
            if (t > 0) {
                for (int q = tid; q < bc * H_; q += 256)
                    hbuf[q] = __ldcg(&hsrc[b0 * H_ + q]);
            }
            __syncthreads();

            float acc[16];
            #pragma unroll
            for (int z = 0; z < 16; z++) acc[z] = 0.f;
            if (t > 0) {
                #pragma unroll
                for (int i = 0; i < 16; i++) {
                    int kk = lane + 32 * i;
                    float w0 = wr[i], w1 = wr[16 + i], w2 = wr[32 + i], w3 = wr[48 + i];
                    #pragma unroll
                    for (int bb = 0; bb < 4; bb++) {
                        float h = hbuf[bb * H_ + kk];
                        acc[bb * 4 + 0] += w0 * h;
                        acc[bb * 4 + 1] += w1 * h;
                        acc[bb * 4 + 2] += w2 * h;
                        acc[bb * 4 + 3] += w3 * h;
                    }
                }
                wred4(acc[0],  acc[1],  acc[2],  acc[3]);
                wred4(acc[4],  acc[5],  acc[6],  acc[7]);
                wred4(acc[8],  acc[9],  acc[10], acc[11]);
                wred4(acc[12], acc[13], acc[14], acc[15]);
            }
            if (lane < bc) {
                int b = b0 + lane;
                float gi = acc[lane * 4 + 0] + pgi;
                float gf = acc[lane * 4 + 1] + pgf;
                float gg = acc[lane * 4 + 2] + pgg;
                float go = acc[lane * 4 + 3] + pgo;
                float cp = (t > 0) ? scll[warp * 32 + b] : 0.f;
                float cn = sigf(gf) * cp + sigf(gi) * tanhf(gg);
                scll[warp * 32 + b] = cn;
                hdst[b * H_ + j] = sigf(go) * tanhf(cn);
            }
            __syncthreads();
        }

        if (tid == 0) {
            __threadfence();
            atomicAdd(&g_bar, 1);
            if (t < P_ - 1 || k == 0) {
                int target = NCTA_ * (t + 1);
                while (*(volatile int*)&g_bar < target) { }
            }
        }
        __syncthreads();
    }

    // ---- final head: CTA 0 only ----
    if (k != 0) return;
    const float* hf = g_h[P_ & 1];   // g_h[0]

    float* buf = sm;                 // [1024]
    float* ys  = sm + 1024;          // [512]
    float* red = sm + 1536;          // [48]
    __syncthreads();

    int o0 = tid & 15,  i0 = tid >> 4;
    int o1 = (tid + 256) & 15, i1 = (tid + 256) >> 4;
    float acc0 = bfc[o0], acc1 = bfc[o1];

    for (int b = 0; b < nv; b++) {
        for (int q = tid; q < H_; q += 256) {
            buf[q]      = __ldcg(&hf[b * H_ + q]);
            buf[H_ + q] = g_hb[b * H_ + q];
        }
        __syncthreads();
        #pragma unroll 8
        for (int jq = 0; jq < 32; jq++) {
            acc0 += buf[i0 * 32 + jq] * __ldg(&Wfc[o0 * (2 * H_) + jq * 32 + b]);
            acc1 += buf[i1 * 32 + jq] * __ldg(&Wfc[o1 * (2 * H_) + jq * 32 + b]);
        }
        __syncthreads();
    }
    ys[tid] = acc0;
    ys[tid + 256] = acc1;
    __syncthreads();

    float* mean_s = red; float* inv_s = red + 16; float* lse_s = red + 32;
    if (tid < O_) {
        float m = 0.f;
        for (int r = 0; r < B_; r++) m += ys[r * O_ + tid];
        m *= (1.f / B_);
        float v = 0.f;
        for (int r = 0; r < B_; r++) { float d = ys[r * O_ + tid] - m; v += d * d; }
        v *= (1.f / B_);
        mean_s[tid] = m;
        inv_s[tid] = 1.f / sqrtf(v + EPS_);
    }
    __syncthreads();

    float y0 = fmaxf(gamma[o0] * (ys[tid] - mean_s[o0]) * inv_s[o0] + beta[o0], 0.f);
    float y1 = fmaxf(gamma[o1] * (ys[tid + 256] - mean_s[o1]) * inv_s[o1] + beta[o1], 0.f);
    __syncthreads();
    ys[tid] = y0; ys[tid + 256] = y1;
    __syncthreads();

    if (tid < O_) {
        float mx = -3e38f;
        for (int r = 0; r < B_; r++) mx = fmaxf(mx, ys[r * O_ + tid]);
        float ss = 0.f;
        for (int r = 0; r < B_; r++) ss += expf(ys[r * O_ + tid] - mx);
        lse_s[tid] = logf(ss) + mx;
    }
    __syncthreads();

    out[i0 * O_ + o0] = ys[tid] - lse_s[o0];
    out[i1 * O_ + o1] = ys[tid + 256] - lse_s[o1];
}

// ---------------- launcher ----------------
extern "C" void kernel_launch(void* const* d_in, const int* in_sizes, int n_in,
                              void* d_out, int out_size)
{
    const int*  x    = (const int*)d_in[0];
    const int*  xm   = (const int*)d_in[1];
    const float* xf  = (const float*)d_in[2];
    const int*  lens = (const int*)d_in[3];
    const float* emb    = (const float*)d_in[6];
    const float* wattn  = (const float*)d_in[7];
    const float* battn  = (const float*)d_in[8];
    const float* Wih_f  = (const float*)d_in[9];
    const float* Whh_f  = (const float*)d_in[10];
    const float* bih_f  = (const float*)d_in[11];
    const float* bhh_f  = (const float*)d_in[12];
    const float* Wih_b  = (const float*)d_in[13];
    const float* bih_b  = (const float*)d_in[15];
    const float* bhh_b  = (const float*)d_in[16];
    const float* Wfc    = (const float*)d_in[17];
    const float* bfc    = (const float*)d_in[18];
    const float* gamma  = (const float*)d_in[19];
    const float* beta   = (const float*)d_in[20];
    float* out = (float*)d_out;

    const int K1_SMEM = (S_ * H_ + S_ * F_ + H_ + 3 * S_) * 4;  // ~113 KB
    const int K2_SMEM = P_ * 2 * D_ * 4;                        // 110592
    const int K3_SMEM = (4 * H_ + 8 * 32) * 4;                  // 9216
    cudaFuncSetAttribute(attn_rep_kernel,
                         cudaFuncAttributeMaxDynamicSharedMemorySize, K1_SMEM);
    cudaFuncSetAttribute(gxbwd_kernel,
                         cudaFuncAttributeMaxDynamicSharedMemorySize, K2_SMEM);
    cudaFuncSetAttribute(lstm_fused_kernel,
                         cudaFuncAttributeMaxDynamicSharedMemorySize, K3_SMEM);

    attn_rep_kernel<<<dim3(P_, 4), 512, K1_SMEM>>>(x, xm, xf, lens, emb,
                                                   wattn, battn);
    gxbwd_kernel<<<GXCTA_ + NCTA_, 256, K2_SMEM>>>(lens, Wih_f, bih_f, bhh_f,
                                                   Wih_b, bih_b, bhh_b);
    lstm_fused_kernel<<<NCTA_, 256, K3_SMEM>>>(lens, Whh_f, Wfc, bfc,
                                               gamma, beta, out);
}

// round 16
// speedup vs baseline: 1.1953x; 1.1953x over previous
#include <cuda_runtime.h>
#include <cstdint>

#define B_ 32
#define P_ 24
#define S_ 48
#define H_ 512
#define F_ 64
#define D_ 576    // H + F
#define G4_ 2048  // 4*H
#define O_ 16
#define EPS_ 1e-5f
#define NCTA_ 64        // lstm CTAs per group
#define GXCTA_ 128      // gx CTAs

// ---------------- scratch (device globals, no allocation) ----------------
__device__ float g_seq[P_ * B_ * D_];     // rep, layout [t][b][d]
__device__ float g_Gx[P_ * B_ * G4_];     // input projection + bias, [t][b][n]
__device__ float g_h[2][B_ * H_];         // ping-pong hidden
__device__ float g_hb[B_ * H_];           // backward first-step hidden
__device__ int   g_bars[2][32];           // per-group barrier counters (128B apart)

__device__ __forceinline__ float sigf(float x) { return 1.f / (1.f + expf(-x)); }
__device__ __forceinline__ float wred(float v) {
    #pragma unroll
    for (int o = 16; o; o >>= 1) v += __shfl_xor_sync(0xffffffffu, v, o);
    return v;
}
__device__ __forceinline__ void wred4(float& a, float& b, float& c, float& d) {
    #pragma unroll
    for (int o = 16; o; o >>= 1) {
        a += __shfl_xor_sync(0xffffffffu, a, o);
        b += __shfl_xor_sync(0xffffffffu, b, o);
        c += __shfl_xor_sync(0xffffffffu, c, o);
        d += __shfl_xor_sync(0xffffffffu, d, o);
    }
}
__device__ __forceinline__ int num_valid(const int* lens) {
    int nv = 0;
    while (nv < B_ && lens[nv] == P_) nv++;
    return nv;
}

// ---------------- K1: attention; grid (P, 4); pipelined cp.async -------------
// (measured 9.0us, unchanged)
__global__ __launch_bounds__(512) void attn_rep_kernel(
    const int* __restrict__ x, const int* __restrict__ xmask,
    const float* __restrict__ xfeat, const int* __restrict__ lens,
    const float* __restrict__ emb, const float* __restrict__ wattn,
    const float* __restrict__ battn)
{
    int p = blockIdx.x;          // 0..23
    int b = blockIdx.y;          // 0..3  (valid batches are a prefix)
    int nv = num_valid(lens);
    if (b >= nv) return;
    int bmax = (b == 3) ? nv : (b + 1);

    extern __shared__ float sm1[];
    float* E     = sm1;               // S*H = 24576
    float* xfs   = E + S_ * H_;       // S*F = 3072
    float* wv    = xfs + S_ * F_;     // 512
    float* sc    = wv + H_;           // 48
    float* alpha = sc + S_;           // 48
    int*   msk   = (int*)(alpha + S_);// 48

    int tid = threadIdx.x;
    int warp = tid >> 5, lane = tid & 31;
    for (int i = tid; i < H_; i += 512) wv[i] = wattn[i];

    for (; b < bmax; b++) {
        int bp = b * P_ + p;
        if (tid < S_) msk[tid] = (xmask[bp * S_ + tid] != 0);  // int32 or f32 bool

        #pragma unroll
        for (int it = 0; it < 6; it++) {
            int idx = tid + it * 512;
            int row = idx >> 7;
            int c4  = idx & 127;
            int tok = __ldg(&x[bp * S_ + row]);
            const float4* src = (const float4*)emb + (size_t)tok * 128 + c4;
            unsigned daddr = (unsigned)__cvta_generic_to_shared(E + idx * 4);
            asm volatile("cp.async.cg.shared.global [%0], [%1], 16;"
                         :: "r"(daddr), "l"(src));
        }
        asm volatile("cp.async.commit_group;");
        #pragma unroll
        for (int it = 6; it < 12; it++) {
            int idx = tid + it * 512;
            int row = idx >> 7;
            int c4  = idx & 127;
            int tok = __ldg(&x[bp * S_ + row]);
            const float4* src = (const float4*)emb + (size_t)tok * 128 + c4;
            unsigned daddr = (unsigned)__cvta_generic_to_shared(E + idx * 4);
            asm volatile("cp.async.cg.shared.global [%0], [%1], 16;"
                         :: "r"(daddr), "l"(src));
        }
        asm volatile("cp.async.commit_group;");
        {
            const float4* xsrc = (const float4*)(xfeat + (size_t)bp * S_ * F_);
            #pragma unroll
            for (int it = 0; it < 2; it++) {
                int idx = tid + it * 512;
                if (idx < 768) {
                    unsigned daddr = (unsigned)__cvta_generic_to_shared(xfs + idx * 4);
                    asm volatile("cp.async.cg.shared.global [%0], [%1], 16;"
                                 :: "r"(daddr), "l"(xsrc + idx));
                }
            }
        }
        asm volatile("cp.async.commit_group;");

        asm volatile("cp.async.wait_group 2;" ::: "memory");
        __syncthreads();
        for (int s = warp; s < 24; s += 16) {
            float acc = 0.f;
            for (int k = lane; k < H_; k += 32) acc += E[s * H_ + k] * wv[k];
            acc = wred(acc);
            if (lane == 0) sc[s] = msk[s] ? -1e30f : (acc + battn[0]);
        }
        asm volatile("cp.async.wait_group 1;" ::: "memory");
        __syncthreads();
        for (int s = 24 + warp; s < S_; s += 16) {
            float acc = 0.f;
            for (int k = lane; k < H_; k += 32) acc += E[s * H_ + k] * wv[k];
            acc = wred(acc);
            if (lane == 0) sc[s] = msk[s] ? -1e30f : (acc + battn[0]);
        }
        __syncthreads();

        if (warp == 0) {
            float v0 = sc[lane];
            float v1 = (lane < 16) ? sc[32 + lane] : -3e38f;
            float m = fmaxf(v0, v1);
            #pragma unroll
            for (int o = 16; o; o >>= 1)
                m = fmaxf(m, __shfl_xor_sync(0xffffffffu, m, o));
            float e0 = expf(v0 - m);
            float e1 = (lane < 16) ? expf(v1 - m) : 0.f;
            float ssum = wred(e0 + e1);
            float inv = 1.f / ssum;
            alpha[lane] = msk[lane] ? 0.f : e0 * inv;
            if (lane < 16) alpha[32 + lane] = msk[32 + lane] ? 0.f : e1 * inv;
        }
        __syncthreads();

        float* outrow = &g_seq[(p * B_ + b) * D_];
        {
            int h = tid;   // 512 threads == H
            float acc = 0.f;
            #pragma unroll 8
            for (int s = 0; s < S_; s++) acc += alpha[s] * E[s * H_ + h];
            outrow[h] = acc;
        }
        if (tid < F_) {
            asm volatile("cp.async.wait_group 0;" ::: "memory");
            float acc = 0.f;
            #pragma unroll 8
            for (int s = 0; s < S_; s++)
                if (!msk[s]) acc += xfs[s * F_ + tid];
            outrow[H_ + tid] = acc;
        }
        asm volatile("cp.async.wait_group 0;" ::: "memory");
        __syncthreads();
    }
}

// ---------------- K2: Gx projection (CTAs 0..127) + backward step (128..191) --
// (R14 version — measured good; resets both group barriers)
__global__ __launch_bounds__(256) void gxbwd_kernel(
    const int* __restrict__ lens,
    const float* __restrict__ Wih_f, const float* __restrict__ bih_f,
    const float* __restrict__ bhh_f,
    const float* __restrict__ Wih_b, const float* __restrict__ bih_b,
    const float* __restrict__ bhh_b)
{
    int tid = threadIdx.x, warp = tid >> 5, lane = tid & 31;
    int nv = num_valid(lens);
    if (blockIdx.x == 0 && tid == 0) { g_bars[0][0] = 0; g_bars[1][0] = 0; }

    if (blockIdx.x < GXCTA_) {
        extern __shared__ float sseq[];   // [24][2][576]
        for (int b0 = 0; b0 < nv; b0 += 2) {
            int bc = (nv - b0) < 2 ? (nv - b0) : 2;
            for (int q = tid; q < P_ * bc * 144; q += 256) {
                int t  = q / (bc * 144);
                int r  = q - t * (bc * 144);
                int bb = r / 144;
                int c4 = r - bb * 144;
                ((float4*)sseq)[(t * 2 + bb) * 144 + c4] =
                    ((const float4*)g_seq)[((size_t)(t * B_ + b0 + bb)) * 144 + c4];
            }
            __syncthreads();

            #pragma unroll
            for (int nn = 0; nn < 2; nn++) {
                int n = blockIdx.x * 16 + warp * 2 + nn;
                float wreg[18];
                #pragma unroll
                for (int i = 0; i < 18; i++)
                    wreg[i] = Wih_f[(size_t)n * D_ + lane + 32 * i];
                float bias = bih_f[n] + bhh_f[n];
                for (int t0 = 0; t0 < P_; t0 += 4) {
                    for (int bb = 0; bb < bc; bb++) {
                        const float* s0 = &sseq[((t0 + 0) * 2 + bb) * D_];
                        const float* s1 = &sseq[((t0 + 1) * 2 + bb) * D_];
                        const float* s2 = &sseq[((t0 + 2) * 2 + bb) * D_];
                        const float* s3 = &sseq[((t0 + 3) * 2 + bb) * D_];
                        float a0 = 0, a1 = 0, a2 = 0, a3 = 0;
                        #pragma unroll
                        for (int i = 0; i < 18; i++) {
                            float w = wreg[i];
                            int kk = lane + 32 * i;
                            a0 += w * s0[kk];
                            a1 += w * s1[kk];
                            a2 += w * s2[kk];
                            a3 += w * s3[kk];
                        }
                        wred4(a0, a1, a2, a3);
                        if (lane == 0) {
                            int b = b0 + bb;
                            g_Gx[((size_t)(t0 + 0) * B_ + b) * G4_ + n] = a0 + bias;
                            g_Gx[((size_t)(t0 + 1) * B_ + b) * G4_ + n] = a1 + bias;
                            g_Gx[((size_t)(t0 + 2) * B_ + b) * G4_ + n] = a2 + bias;
                            g_Gx[((size_t)(t0 + 3) * B_ + b) * G4_ + n] = a3 + bias;
                        }
                    }
                }
            }
            __syncthreads();
        }
    } else {
        // ---- backward single-step path (h0=c0=0): 64 CTAs x 8 warps ----
        int j = (blockIdx.x - GXCTA_) * 8 + warp;
        const float4* wi4 = (const float4*)(Wih_b + (size_t)j * D_);
        const float4* wg4 = (const float4*)(Wih_b + (size_t)(2 * H_ + j) * D_);
        const float4* wo4 = (const float4*)(Wih_b + (size_t)(3 * H_ + j) * D_);

        for (int b = 0; b < nv; b++) {
            const float4* xr4 = (const float4*)&g_seq[((P_ - 1) * B_ + b) * D_];
            float ai = 0, ag = 0, ao = 0;
            #pragma unroll
            for (int u = 0; u < 5; u++) {
                int i = lane + 32 * u;
                if (i < 144) {
                    float4 xv = xr4[i];
                    float4 a = wi4[i]; ai += a.x*xv.x + a.y*xv.y + a.z*xv.z + a.w*xv.w;
                    float4 c = wg4[i]; ag += c.x*xv.x + c.y*xv.y + c.z*xv.z + c.w*xv.w;
                    float4 d = wo4[i]; ao += d.x*xv.x + d.y*xv.y + d.z*xv.z + d.w*xv.w;
                }
            }
            float dummy = 0.f;
            wred4(ai, ag, ao, dummy);
            if (lane == 0) {
                float bi = bih_b[j] + bhh_b[j];
                float bg = bih_b[2 * H_ + j] + bhh_b[2 * H_ + j];
                float bo = bih_b[3 * H_ + j] + bhh_b[3 * H_ + j];
                float cnew = sigf(ai + bi) * tanhf(ag + bg);   // c_prev = 0
                g_hb[b * H_ + j] = sigf(ao + bo) * tanhf(cnew);
            }
        }
    }
}

// ---------------- K3: fused 24-step LSTM + final head (persistent) -----------
// Two independent CTA groups (batch-parallel): group g = blockIdx/64 owns
// batches b ≡ g (mod 2). Per-group barrier; no cross-group sync until head.
__global__ __launch_bounds__(256) void lstm_fused_kernel(
    const int* __restrict__ lens, const float* __restrict__ Whh,
    const float* __restrict__ Wfc, const float* __restrict__ bfc,
    const float* __restrict__ gamma, const float* __restrict__ beta,
    float* __restrict__ out)
{
    extern __shared__ float sm[];
    float* hbuf = sm;                 // [4][512]
    float* scll = sm + 4 * H_;        // c state [8 warps][32 b]
    int tid = threadIdx.x, warp = tid >> 5, lane = tid & 31;
    int group = blockIdx.x >> 6;      // 0 or 1
    int kk = blockIdx.x & 63;

    int nv = num_valid(lens);
    if (group == 1 && nv < 2) return;   // group 1 idle when single batch
    int j = kk * 8 + warp;

    // owned batches: group, group+2, ... < nv
    int m = 0;
    for (int b = group; b < nv; b += 2) m++;

    float wr[64];
    #pragma unroll
    for (int g = 0; g < 4; g++) {
        const float* row = Whh + (size_t)(g * H_ + j) * H_;
        #pragma unroll
        for (int i = 0; i < 16; i++)
            wr[g * 16 + i] = __ldg(&row[lane + 32 * i]);
    }

    volatile int* mybar = &g_bars[group][0];

    for (int t = 0; t < P_; t++) {
        const float* hsrc = g_h[t & 1];
        float* hdst = g_h[(t + 1) & 1];

        for (int c0 = 0; c0 < m; c0 += 4) {
            int mc = (m - c0) < 4 ? (m - c0) : 4;

            // lane0 prefetches Gx for each owned batch in this chunk
            float pgi[4], pgf[4], pgg[4], pgo[4];
            if (lane == 0) {
                #pragma unroll
                for (int bb = 0; bb < 4; bb++) {
                    if (bb < mc) {
                        int b = group + 2 * (c0 + bb);
                        const float* gx = &g_Gx[((size_t)t * B_ + b) * G4_];
                        pgi[bb] = __ldcg(&gx[j]);
                        pgf[bb] = __ldcg(&gx[H_ + j]);
                        pgg[bb] = __ldcg(&gx[2 * H_ + j]);
                        pgo[bb] = __ldcg(&gx[3 * H_ + j]);
                    }
                }
            }
            if (t > 0) {
                for (int q = tid; q < mc * H_; q += 256) {
                    int bb = q >> 9;
                    int b = group + 2 * (c0 + bb);
                    hbuf[q] = __ldcg(&hsrc[b * H_ + (q & 511)]);
                }
            }
            __syncthreads();
            for (int bb = 0; bb < mc; bb++) {
                float ai = 0, af = 0, ag = 0, ao = 0;
                if (t > 0) {
                    const float* hp = &hbuf[bb * H_];
                    float hr[16];
                    #pragma unroll
                    for (int i = 0; i < 16; i++) hr[i] = hp[lane + 32 * i];
                    #pragma unroll
                    for (int i = 0; i < 16; i++) {
                        ai += wr[i]      * hr[i];
                        af += wr[16 + i] * hr[i];
                        ag += wr[32 + i] * hr[i];
                        ao += wr[48 + i] * hr[i];
                    }
                    wred4(ai, af, ag, ao);
                }
                if (lane == 0) {
                    int b = group + 2 * (c0 + bb);
                    float gi = ai + pgi[bb];
                    float gf = af + pgf[bb];
                    float gg = ag + pgg[bb];
                    float go = ao + pgo[bb];
                    float cp = (t > 0) ? scll[warp * 32 + b] : 0.f;
                    float cn = sigf(gf) * cp + sigf(gi) * tanhf(gg);
                    scll[warp * 32 + b] = cn;
                    hdst[b * H_ + j] = sigf(go) * tanhf(cn);
                }
            }
            __syncthreads();
        }

        // per-group grid barrier
        if (tid == 0) {
            __threadfence();
            atomicAdd((int*)mybar, 1);
            if (t < P_ - 1 || (group == 0 && kk == 0)) {
                int target = NCTA_ * (t + 1);
                while (*mybar < target) { }
            }
        }
        __syncthreads();
    }

    // ---- final head: group 0 CTA 0 only ----
    if (group != 0 || kk != 0) return;
    if (nv > 1) {   // wait for group 1's final step
        if (tid == 0) {
            while (*(volatile int*)&g_bars[1][0] < NCTA_ * P_) { }
        }
        __syncthreads();
    }
    const float* hf = g_h[P_ & 1];   // g_h[0]

    float* buf = sm;                 // [1024]
    float* ys  = sm + 1024;          // [512]
    float* red = sm + 1536;          // [48]
    __syncthreads();

    int o0 = tid & 15,  i0 = tid >> 4;
    int o1 = (tid + 256) & 15, i1 = (tid + 256) >> 4;
    float acc0 = bfc[o0], acc1 = bfc[o1];

    for (int b = 0; b < nv; b++) {
        for (int q = tid; q < H_; q += 256) {
            buf[q]      = __ldcg(&hf[b * H_ + q]);
            buf[H_ + q] = g_hb[b * H_ + q];
        }
        __syncthreads();
        #pragma unroll 8
        for (int jq = 0; jq < 32; jq++) {
            acc0 += buf[i0 * 32 + jq] * __ldg(&Wfc[o0 * (2 * H_) + jq * 32 + b]);
            acc1 += buf[i1 * 32 + jq] * __ldg(&Wfc[o1 * (2 * H_) + jq * 32 + b]);
        }
        __syncthreads();
    }
    ys[tid] = acc0;
    ys[tid + 256] = acc1;
    __syncthreads();

    float* mean_s = red; float* inv_s = red + 16; float* lse_s = red + 32;
    if (tid < O_) {
        float m2 = 0.f;
        for (int r = 0; r < B_; r++) m2 += ys[r * O_ + tid];
        m2 *= (1.f / B_);
        float v = 0.f;
        for (int r = 0; r < B_; r++) { float d = ys[r * O_ + tid] - m2; v += d * d; }
        v *= (1.f / B_);
        mean_s[tid] = m2;
        inv_s[tid] = 1.f / sqrtf(v + EPS_);
    }
    __syncthreads();

    float y0 = fmaxf(gamma[o0] * (ys[tid] - mean_s[o0]) * inv_s[o0] + beta[o0], 0.f);
    float y1 = fmaxf(gamma[o1] * (ys[tid + 256] - mean_s[o1]) * inv_s[o1] + beta[o1], 0.f);
    __syncthreads();
    ys[tid] = y0; ys[tid + 256] = y1;
    __syncthreads();

    if (tid < O_) {
        float mx = -3e38f;
        for (int r = 0; r < B_; r++) mx = fmaxf(mx, ys[r * O_ + tid]);
        float ss = 0.f;
        for (int r = 0; r < B_; r++) ss += expf(ys[r * O_ + tid] - mx);
        lse_s[tid] = logf(ss) + mx;
    }
    __syncthreads();

    out[i0 * O_ + o0] = ys[tid] - lse_s[o0];
    out[i1 * O_ + o1] = ys[tid + 256] - lse_s[o1];
}

// ---------------- launcher ----------------
extern "C" void kernel_launch(void* const* d_in, const int* in_sizes, int n_in,
                              void* d_out, int out_size)
{
    const int*  x    = (const int*)d_in[0];
    const int*  xm   = (const int*)d_in[1];
    const float* xf  = (const float*)d_in[2];
    const int*  lens = (const int*)d_in[3];
    const float* emb    = (const float*)d_in[6];
    const float* wattn  = (const float*)d_in[7];
    const float* battn  = (const float*)d_in[8];
    const float* Wih_f  = (const float*)d_in[9];
    const float* Whh_f  = (const float*)d_in[10];
    const float* bih_f  = (const float*)d_in[11];
    const float* bhh_f  = (const float*)d_in[12];
    const float* Wih_b  = (const float*)d_in[13];
    const float* bih_b  = (const float*)d_in[15];
    const float* bhh_b  = (const float*)d_in[16];
    const float* Wfc    = (const float*)d_in[17];
    const float* bfc    = (const float*)d_in[18];
    const float* gamma  = (const float*)d_in[19];
    const float* beta   = (const float*)d_in[20];
    float* out = (float*)d_out;

    const int K1_SMEM = (S_ * H_ + S_ * F_ + H_ + 3 * S_) * 4;  // ~113 KB
    const int K2_SMEM = P_ * 2 * D_ * 4;                        // 110592
    const int K3_SMEM = (4 * H_ + 8 * 32) * 4;                  // 9216
    cudaFuncSetAttribute(attn_rep_kernel,
                         cudaFuncAttributeMaxDynamicSharedMemorySize, K1_SMEM);
    cudaFuncSetAttribute(gxbwd_kernel,
                         cudaFuncAttributeMaxDynamicSharedMemorySize, K2_SMEM);
    cudaFuncSetAttribute(lstm_fused_kernel,
                         cudaFuncAttributeMaxDynamicSharedMemorySize, K3_SMEM);

    attn_rep_kernel<<<dim3(P_, 4), 512, K1_SMEM>>>(x, xm, xf, lens, emb,
                                                   wattn, battn);
    gxbwd_kernel<<<GXCTA_ + NCTA_, 256, K2_SMEM>>>(lens, Wih_f, bih_f, bhh_f,
                                                   Wih_b, bih_b, bhh_b);
    lstm_fused_kernel<<<2 * NCTA_, 256, K3_SMEM>>>(lens, Whh_f, Wfc, bfc,
                                                   gamma, beta, out);
}